// round 14
// baseline (speedup 1.0000x reference)
#include <cuda_runtime.h>
#include <stdint.h>

#define BATCH   8
#define NPRIOR  33600
#define TOPK    5000
#define KEEPK   750
#define CONF_TH 0.3f
#define NMS_TH  0.3f
#define NB      4096
#define CANDS   6144
#define BINSCALE (4094.0f / 0.7f)
#define KEYTH   0xBE99999Au     // key_from_float(0.3f)

#define NCOL    20
#define COLCAP  160
#define LARGECAP 256
#define INVCOLW (1.0f / 64.0f)
#define SPAD    5120            // TOPK padded to chunk multiple (128)

typedef unsigned long long ull;

// ---------------- device scratch ----------------
__device__ int    g_bincur[BATCH * NB];
__device__ int    g_suf[BATCH * (NB + 2)];
__device__ int    g_cb[BATCH];
__device__ int    g_ctot[BATCH];
__device__ ull    g_cand[(size_t)BATCH * CANDS];
__device__ ull    g_top [(size_t)BATCH * TOPK];

// ---------------- helpers ----------------
__device__ __forceinline__ unsigned key_from_float(float f) {
    unsigned u = __float_as_uint(f);
    return (u & 0x80000000u) ? ~u : (u | 0x80000000u);
}
__device__ __forceinline__ float float_from_key(unsigned u) {
    return __uint_as_float((u & 0x80000000u) ? (u ^ 0x80000000u) : ~u);
}
__device__ __forceinline__ int bin_of(float m) {
    if (!(m > CONF_TH)) return 0;
    int b = (int)((m - CONF_TH) * BINSCALE);
    if (b > 4094) b = 4094;
    return 1 + b;
}
__device__ __forceinline__ int colclamp(float x) {
    int c = (int)floorf(x * INVCOLW);
    return c < 0 ? 0 : (c > NCOL - 1 ? NCOL - 1 : c);
}
// box = (x1,x2,y1,y2); w,h>0 so reference clamps are identity; division exact
__device__ __forceinline__ bool pair_sup(float4 a, float4 b, float ab) {
    float xo = fminf(a.y, b.y) - fmaxf(a.x, b.x);
    float yo = fminf(a.w, b.w) - fmaxf(a.z, b.z);
    if (xo > 0.0f && yo > 0.0f) {
        float inter = xo * yo;
        float aa = (a.y - a.x) * (a.w - a.z);
        return inter / (aa + ab - inter + 1e-12f) > NMS_TH;
    }
    return false;
}
__device__ __forceinline__ void prior_of(unsigned idx, float& px, float& py, float& ps) {
    if (idx < 25600u)      { ps = 8.0f;  px = (float)((idx % 160u) * 8u); py = (float)((idx / 160u) * 8u); }
    else if (idx < 32000u) { unsigned j = idx - 25600u; ps = 16.0f; px = (float)((j % 80u) * 16u); py = (float)((j / 80u) * 16u); }
    else                   { unsigned j = idx - 32000u; ps = 32.0f; px = (float)((j % 40u) * 32u); py = (float)((j / 40u) * 32u); }
}

// ---------------- K2: shared-mem histogram + suffix scan + cutoff ----------------
__global__ __launch_bounds__(1024, 1)
void k2_scan(const float* __restrict__ cls, const float* __restrict__ obj) {
    __shared__ int hist[NB];
    __shared__ int suf[NB];
    __shared__ int wsum[32];
    __shared__ int sh_cb;
    const int b = blockIdx.x, tid = threadIdx.x;
    const int lane = tid & 31, warp = tid >> 5;

    for (int i = tid; i < NB; i += 1024) hist[i] = 0;
    if (tid == 0) sh_cb = 0;
    __syncthreads();

    // histogram this batch's scores (shared atomics; loads fully MLP-hidden)
    const size_t bb4 = (size_t)b * NPRIOR;
    for (int t4 = tid; t4 < NPRIOR / 4; t4 += 1024) {
        float4 c = *(const float4*)(cls + bb4 + t4 * 4);
        float4 o = *(const float4*)(obj + bb4 + t4 * 4);
        float sv[4] = {sqrtf(c.x * o.x), sqrtf(c.y * o.y), sqrtf(c.z * o.z), sqrtf(c.w * o.w)};
#pragma unroll
        for (int j = 0; j < 4; j++)
            if (sv[j] > CONF_TH) atomicAdd(&hist[bin_of(sv[j])], 1);
    }
    __syncthreads();

    int rbase = tid * 4;
    int v[4];
#pragma unroll
    for (int j = 0; j < 4; j++) v[j] = hist[NB - 1 - (rbase + j)];
    v[1] += v[0]; v[2] += v[1]; v[3] += v[2];
    int tot = v[3];
#pragma unroll
    for (int o = 1; o < 32; o <<= 1) {
        int n = __shfl_up_sync(0xffffffffu, tot, o);
        if (lane >= o) tot += n;
    }
    if (lane == 31) wsum[warp] = tot;
    __syncthreads();
    if (warp == 0) {
        int w = wsum[lane];
#pragma unroll
        for (int o = 1; o < 32; o <<= 1) {
            int n = __shfl_up_sync(0xffffffffu, w, o);
            if (lane >= o) w += n;
        }
        wsum[lane] = w;
    }
    __syncthreads();
    int pre = (warp ? wsum[warp - 1] : 0) + (tot - v[3]);
#pragma unroll
    for (int j = 0; j < 4; j++) suf[NB - 1 - (rbase + j)] = pre + v[j];
    __syncthreads();
    if (tid == 0) suf[0] = NPRIOR;
    __syncthreads();
    int local = -1;
#pragma unroll
    for (int j = 0; j < 4; j++) {
        int bin = NB - 1 - (rbase + j);
        if (bin >= 1 && suf[bin] >= TOPK && bin > local) local = bin;
    }
    if (local >= 0) atomicMax(&sh_cb, local);
    __syncthreads();
    int cb = sh_cb; if (cb < 1) cb = 1;
    int ctot = suf[cb]; if (ctot > CANDS) ctot = CANDS;
    if (tid == 0) {
        g_cb[b] = cb;
        g_ctot[b] = ctot;
        g_suf[b * (NB + 2) + NB] = 0;
        g_suf[b * (NB + 2) + NB + 1] = 0;
    }
    for (int i = tid; i < NB; i += 1024) {
        g_suf[b * (NB + 2) + i] = suf[i];
        g_bincur[b * NB + i] = 0;
    }
    // tail zero (only if fewer than TOPK candidates exist); zero-key -> invalid in k5
    for (int r = ctot + tid; r < TOPK; r += 1024)
        g_top[(size_t)b * TOPK + r] = 0ull;
}

// ---------------- K3: recompute keys from cls/obj, scatter to g_cand ----------------
__global__ void k3_compact(const float* __restrict__ cls, const float* __restrict__ obj) {
    int t4 = blockIdx.x * blockDim.x + threadIdx.x;
    if (t4 >= BATCH * NPRIOR / 4) return;
    int base = t4 * 4;
    int b = base / NPRIOR;           // NPRIOR % 4 == 0 -> all 4 in same batch
    int i0 = base - b * NPRIOR;
    int cb = g_cb[b];
    float4 c = *(const float4*)(cls + base);
    float4 o = *(const float4*)(obj + base);
    float sv[4] = {sqrtf(c.x * o.x), sqrtf(c.y * o.y), sqrtf(c.z * o.z), sqrtf(c.w * o.w)};
#pragma unroll
    for (int j = 0; j < 4; j++) {
        float m = sv[j];
        if (!(m > CONF_TH)) continue;
        int bin = bin_of(m);
        if (bin < cb) continue;
        int pos = g_suf[b * (NB + 2) + bin + 1] + atomicAdd(&g_bincur[b * NB + bin], 1);
        if (pos < CANDS) {
            ull key = ((ull)key_from_float(m) << 32) | (unsigned)(~(unsigned)(i0 + j));
            g_cand[(size_t)b * CANDS + pos] = key;
        }
    }
}

// ---------------- K4: exact in-bin rank -> g_top (keys only, no decode) ----------------
__global__ void k4_rank() {
    int t = blockIdx.x * blockDim.x + threadIdx.x;
    int b = t / CANDS;
    if (b >= BATCH) return;
    int s = t - b * CANDS;
    int ct = g_ctot[b];
    if (s >= ct) return;
    const ull* cand = g_cand + (size_t)b * CANDS;
    ull key = __ldg(cand + s);
    float m = float_from_key((unsigned)(key >> 32));
    int bin = bin_of(m);
    const int* suf = g_suf + b * (NB + 2);
    int st = suf[bin + 1];
    int en = suf[bin]; if (en > ct) en = ct;
    int r = st;
    for (int q = st; q < en; q++)
        if (__ldg(cand + q) > key) r++;
    if (r >= TOPK) return;
    g_top[(size_t)b * TOPK + r] = key;
}

// ---------------- K5: decode + NMS + filler + output ----------------
#define OFF_SBOX   0                      // float4[5120] = 81920
#define OFF_SVAL   81920                  // u8[5120]     = 5120
#define OFF_COLBOX 87040                  // float4[20*160] = 51200
#define OFF_LARGE  138240                 // float4[256]  = 4096
#define OFF_KPOS   142336                 // u16[896]     = 1792
#define OFF_KEEPF  144128                 // u8[5000]     = 5000
#define SMEM_K5    149128

extern __shared__ char smem[];

__global__ __launch_bounds__(1024, 1)
void k5_nms(const float* __restrict__ bbox, const float* __restrict__ kps,
            float* __restrict__ out, int write_valid) {
    float4* sbox  = (float4*)(smem + OFF_SBOX);
    unsigned char* svalid = (unsigned char*)(smem + OFF_SVAL);
    float4* colbox= (float4*)(smem + OFF_COLBOX);
    float4* large = (float4*)(smem + OFF_LARGE);
    unsigned short* kpos = (unsigned short*)(smem + OFF_KPOS);
    unsigned char*  keepf= (unsigned char*) (smem + OFF_KEEPF);

    __shared__ int wsum[32];
    __shared__ ull ovLoS[128];
    __shared__ ull ovHiS[128];
    __shared__ unsigned char statS[128];
    __shared__ int keptCount;
    __shared__ int colcnt[NCOL];
    __shared__ int lcnt;

    const int b = blockIdx.x, tid = threadIdx.x;
    const int lane = tid & 31, warp = tid >> 5;
    const size_t bT = (size_t)b * TOPK;
    const size_t boff = (size_t)b * NPRIOR;

    // prefetch: load keys, decode boxes directly (gathers MLP-hidden)
    for (int i = tid; i < TOPK; i += 1024) {
        ull key = g_top[bT + i];
        unsigned hk = (unsigned)(key >> 32);
        bool val = hk > KEYTH;
        svalid[i] = val ? 1 : 0;
        keepf[i] = 0;
        float4 bx = make_float4(0.f, 0.f, 0.f, 0.f);
        if (val) {
            unsigned idx = ~(unsigned)key;
            float px, py, ps; prior_of(idx, px, py, ps);
            const float* bb = bbox + (boff + idx) * 4;
            float cx = px + bb[0] * ps;
            float cy = py + bb[1] * ps;
            float w  = ps * expf(bb[2]);
            float h  = ps * expf(bb[3]);
            float x1 = cx - w * 0.5f, y1 = cy - h * 0.5f;
            bx = make_float4(x1, x1 + w, y1, y1 + h);
        }
        sbox[i] = bx;
    }
    for (int i = TOPK + tid; i < SPAD; i += 1024) {
        sbox[i] = make_float4(0.f, 0.f, 0.f, 0.f);
        svalid[i] = 0;
    }
    if (tid == 0) { keptCount = 0; lcnt = 0; }
    if (tid < NCOL) colcnt[tid] = 0;
    __syncthreads();

    for (int base = 0; base < TOPK; base += 128) {
#pragma unroll
        for (int q = 0; q < 4; q++) {
            const int ci = q * 32 + warp;
            const int p = base + ci;
            float4 bj = sbox[p];
            float aj = (bj.y - bj.x) * (bj.w - bj.z);
            unsigned m0 = 0, m1 = 0, m2 = 0, m3 = 0;
            for (int q2 = 0; q2 <= q; q2++) {
                bool ob;
                if (q2 < q) ob = pair_sup(sbox[base + q2 * 32 + lane], bj, aj);
                else        ob = (lane < warp) ? pair_sup(sbox[base + q * 32 + lane], bj, aj) : false;
                unsigned bal = __ballot_sync(0xffffffffu, ob);
                if (q2 == 0) m0 = bal; else if (q2 == 1) m1 = bal;
                else if (q2 == 2) m2 = bal; else m3 = bal;
            }
            bool sup = false;
            int c0 = colclamp(bj.x), c1 = colclamp(bj.y);
            for (int c = c0; c <= c1; c++) {
                int n = colcnt[c];
                const float4* cp = colbox + c * COLCAP;
                for (int m = lane; m < n; m += 32)
                    sup |= pair_sup(cp[m], bj, aj);
            }
            {
                int n = lcnt;
                for (int m = lane; m < n; m += 32)
                    sup |= pair_sup(large[m], bj, aj);
            }
            sup = __any_sync(0xffffffffu, sup);
            if (lane == 0) {
                ovLoS[ci] = (ull)m0 | ((ull)m1 << 32);
                ovHiS[ci] = (ull)m2 | ((ull)m3 << 32);
                statS[ci] = (svalid[p] && !sup) ? 1 : 0;
            }
        }
        __syncthreads();

        if (warp == 0) {
            unsigned s0 = __ballot_sync(0xffffffffu, statS[lane]);
            unsigned s1 = __ballot_sync(0xffffffffu, statS[32 + lane]);
            unsigned s2 = __ballot_sync(0xffffffffu, statS[64 + lane]);
            unsigned s3 = __ballot_sync(0xffffffffu, statS[96 + lane]);
            ull aliveLo = (ull)s0 | ((ull)s1 << 32);
            ull aliveHi = (ull)s2 | ((ull)s3 << 32);
            bool cf0, cf1, cf2, cf3;
            {
                int i0 = lane, i1 = 32 + lane, i2 = 64 + lane, i3 = 96 + lane;
                cf0 = ((aliveLo >> i0) & 1ull) && ((ovLoS[i0] & aliveLo) | (ovHiS[i0] & aliveHi));
                cf1 = ((aliveLo >> i1) & 1ull) && ((ovLoS[i1] & aliveLo) | (ovHiS[i1] & aliveHi));
                cf2 = ((aliveHi >> (i2 - 64)) & 1ull) && ((ovLoS[i2] & aliveLo) | (ovHiS[i2] & aliveHi));
                cf3 = ((aliveHi >> (i3 - 64)) & 1ull) && ((ovLoS[i3] & aliveLo) | (ovHiS[i3] & aliveHi));
            }
            unsigned c0b = __ballot_sync(0xffffffffu, cf0);
            unsigned c1b = __ballot_sync(0xffffffffu, cf1);
            unsigned c2b = __ballot_sync(0xffffffffu, cf2);
            unsigned c3b = __ballot_sync(0xffffffffu, cf3);
            ull confLo = (ull)c0b | ((ull)c1b << 32);
            ull confHi = (ull)c2b | ((ull)c3b << 32);
            ull keepLo = aliveLo & ~confLo;
            ull keepHi = aliveHi & ~confHi;
            ull pLo = confLo, pHi = confHi;
            while (pLo | pHi) {
                int i;
                if (pLo) { i = __ffsll((long long)pLo) - 1; pLo &= pLo - 1; }
                else     { i = 64 + __ffsll((long long)pHi) - 1; pHi &= pHi - 1; }
                if (((ovLoS[i] & keepLo) | (ovHiS[i] & keepHi)) == 0ull) {
                    if (i < 64) keepLo |= 1ull << i; else keepHi |= 1ull << (i - 64);
                }
            }
            int b0 = keptCount;
            int totalKeep = __popcll(keepLo) + __popcll(keepHi);
            int nLo = __popcll(keepLo);
#pragma unroll
            for (int k = 0; k < 4; k++) {
                int ci = k * 32 + lane;
                int p = base + ci;
                bool kk = (ci < 64) ? ((keepLo >> ci) & 1ull) : ((keepHi >> (ci - 64)) & 1ull);
                if (p < TOPK) keepf[p] = kk ? 1 : 0;
                if (kk) {
                    int off = (ci < 64) ? __popcll(keepLo & ((1ull << ci) - 1ull))
                                        : nLo + __popcll(keepHi & ((1ull << (ci - 64)) - 1ull));
                    kpos[b0 + off] = (unsigned short)p;
                    float4 bl = sbox[p];
                    int cc0 = colclamp(bl.x), cc1 = colclamp(bl.y);
                    if (cc1 - cc0 >= 3) {
                        int d = atomicAdd(&lcnt, 1);
                        if (d < LARGECAP) large[d] = bl;
                    } else {
                        for (int c = cc0; c <= cc1; c++) {
                            int d = atomicAdd(&colcnt[c], 1);
                            if (d < COLCAP) colbox[c * COLCAP + d] = bl;
                            else { int e = atomicAdd(&lcnt, 1); if (e < LARGECAP) large[e] = bl; }
                        }
                    }
                }
            }
            if (lane == 0) keptCount = b0 + totalKeep;
        }
        __syncthreads();
        if (keptCount >= KEEPK) break;
    }
    __syncthreads();

    int kc = keptCount;
    int kout = kc < KEEPK ? kc : KEEPK;

    // parallel filler: first (KEEPK-kc) non-kept positions, in order
    if (kc < KEEPK) {
        int need = KEEPK - kc;
        int j0 = tid * 5;
        int cnt = 0;
#pragma unroll
        for (int j = 0; j < 5; j++) {
            int p = j0 + j;
            if (p < TOPK && !keepf[p]) cnt++;
        }
        int x = cnt;
#pragma unroll
        for (int o = 1; o < 32; o <<= 1) {
            int n = __shfl_up_sync(0xffffffffu, x, o);
            if (lane >= o) x += n;
        }
        if (lane == 31) wsum[warp] = x;
        __syncthreads();
        if (warp == 0) {
            int w = wsum[lane];
#pragma unroll
            for (int o = 1; o < 32; o <<= 1) {
                int n = __shfl_up_sync(0xffffffffu, w, o);
                if (lane >= o) w += n;
            }
            wsum[lane] = w;
        }
        __syncthreads();
        int pre = (warp ? wsum[warp - 1] : 0) + (x - cnt);
#pragma unroll
        for (int j = 0; j < 5; j++) {
            int p = j0 + j;
            if (p < TOPK && !keepf[p]) {
                if (pre < need) kpos[kc + pre] = (unsigned short)p;
                pre++;
            }
        }
    }
    __syncthreads();

    // write final 750 rows
    for (int r = tid; r < KEEPK; r += 1024) {
        int pos = kpos[r];
        ull key = g_top[bT + pos];
        unsigned idx = ~(unsigned)key;
        unsigned hk = (unsigned)(key >> 32);
        float score = __uint_as_float((hk & 0x80000000u) ? (hk ^ 0x80000000u) : ~hk);
        float px, py, ps; prior_of(idx, px, py, ps);
        const float* bb = bbox + (boff + idx) * 4;
        float cx = px + bb[0] * ps, cy = py + bb[1] * ps;
        float w = ps * expf(bb[2]), h = ps * expf(bb[3]);
        float x1 = cx - w * 0.5f, y1 = cy - h * 0.5f;
        size_t t = (size_t)b * KEEPK + r;
        float* o = out + t * 15;
        o[0] = x1; o[1] = y1; o[2] = x1 + w; o[3] = y1 + h;
        const float* kp = kps + (boff + idx) * 10;
#pragma unroll
        for (int m = 0; m < 5; m++) {
            o[4 + 2 * m] = px + kp[2 * m] * ps;
            o[5 + 2 * m] = py + kp[2 * m + 1] * ps;
        }
        o[14] = score;
        if (write_valid)
            out[(size_t)BATCH * KEEPK * 15 + t] = (r < kout) ? 1.0f : 0.0f;
    }
}

// ---------------- launch ----------------
extern "C" void kernel_launch(void* const* d_in, const int* in_sizes, int n_in,
                              void* d_out, int out_size) {
    const float* cls  = (const float*)d_in[0];
    const float* obj  = (const float*)d_in[1];
    const float* bbox = (const float*)d_in[2];
    const float* kps  = (const float*)d_in[3];
    float* out = (float*)d_out;

    static int attr_set = 0;
    if (!attr_set) {
        cudaFuncSetAttribute(k5_nms, cudaFuncAttributeMaxDynamicSharedMemorySize, SMEM_K5);
        attr_set = 1;
    }

    k2_scan<<<BATCH, 1024>>>(cls, obj);
    k3_compact<<<(BATCH * NPRIOR / 4 + 255) / 256, 256>>>(cls, obj);
    k4_rank<<<(BATCH * CANDS + 511) / 512, 512>>>();

    int write_valid = (out_size >= BATCH * KEEPK * 16) ? 1 : 0;
    k5_nms<<<BATCH, 1024, SMEM_K5>>>(bbox, kps, out, write_valid);
}

// round 15
// speedup vs baseline: 1.0315x; 1.0315x over previous
#include <cuda_runtime.h>
#include <stdint.h>

#define BATCH   8
#define NPRIOR  33600
#define TOPK    5000
#define KEEPK   750
#define CONF_TH 0.3f
#define NMS_TH  0.3f
#define NB      4096
#define CANDS   6144
#define BINSCALE (4094.0f / 0.7f)
#define KEYTH   0xBE99999Au     // key_from_float(0.3f)

#define NCOL    20
#define COLCAP  160
#define LARGECAP 256
#define INVCOLW (1.0f / 64.0f)
#define SPAD    5120            // TOPK padded to chunk multiple (128)

typedef unsigned long long ull;

// ---------------- device scratch ----------------
__device__ int    g_hist[BATCH * NB];        // zero at load; every pass restores zero
__device__ int    g_bincur[BATCH * NB];
__device__ int    g_suf[BATCH * (NB + 2)];
__device__ int    g_cb[BATCH];
__device__ int    g_ctot[BATCH];
__device__ ull    g_cand[(size_t)BATCH * CANDS];
__device__ ull    g_top [(size_t)BATCH * TOPK];
__device__ float4 g_boxes[(size_t)BATCH * TOPK];

// ---------------- helpers ----------------
__device__ __forceinline__ unsigned key_from_float(float f) {
    unsigned u = __float_as_uint(f);
    return (u & 0x80000000u) ? ~u : (u | 0x80000000u);
}
__device__ __forceinline__ float float_from_key(unsigned u) {
    return __uint_as_float((u & 0x80000000u) ? (u ^ 0x80000000u) : ~u);
}
__device__ __forceinline__ int bin_of(float m) {
    if (!(m > CONF_TH)) return 0;
    int b = (int)((m - CONF_TH) * BINSCALE);
    if (b > 4094) b = 4094;
    return 1 + b;
}
__device__ __forceinline__ int colclamp(float x) {
    int c = (int)floorf(x * INVCOLW);
    return c < 0 ? 0 : (c > NCOL - 1 ? NCOL - 1 : c);
}
// box = (x1,x2,y1,y2); w,h>0 so reference clamps are identity; division exact
__device__ __forceinline__ bool pair_sup(float4 a, float4 b, float ab) {
    float xo = fminf(a.y, b.y) - fmaxf(a.x, b.x);
    float yo = fminf(a.w, b.w) - fmaxf(a.z, b.z);
    if (xo > 0.0f && yo > 0.0f) {
        float inter = xo * yo;
        float aa = (a.y - a.x) * (a.w - a.z);
        return inter / (aa + ab - inter + 1e-12f) > NMS_TH;
    }
    return false;
}
__device__ __forceinline__ void prior_of(unsigned idx, float& px, float& py, float& ps) {
    if (idx < 25600u)      { ps = 8.0f;  px = (float)((idx % 160u) * 8u); py = (float)((idx / 160u) * 8u); }
    else if (idx < 32000u) { unsigned j = idx - 25600u; ps = 16.0f; px = (float)((j % 80u) * 16u); py = (float)((j / 80u) * 16u); }
    else                   { unsigned j = idx - 32000u; ps = 32.0f; px = (float)((j % 40u) * 32u); py = (float)((j / 40u) * 32u); }
}

// ---------------- K1: histogram only (no key store) ----------------
__global__ void k1_hist(const float* __restrict__ cls, const float* __restrict__ obj) {
    int t4 = blockIdx.x * blockDim.x + threadIdx.x;
    if (t4 >= BATCH * NPRIOR / 4) return;
    int base = t4 * 4;
    int b = base / NPRIOR;           // NPRIOR % 4 == 0 -> all 4 in same batch
    float4 c = *(const float4*)(cls + base);
    float4 o = *(const float4*)(obj + base);
    float sv[4] = {sqrtf(c.x * o.x), sqrtf(c.y * o.y), sqrtf(c.z * o.z), sqrtf(c.w * o.w)};
#pragma unroll
    for (int j = 0; j < 4; j++)
        if (sv[j] > CONF_TH) atomicAdd(&g_hist[b * NB + bin_of(sv[j])], 1);
}

// ---------------- K2: suffix scan + cutoff; re-zeros g_hist ----------------
__global__ __launch_bounds__(1024, 1) void k2_scan() {
    __shared__ int suf[NB];
    __shared__ int wsum[32];
    __shared__ int sh_cb;
    const int b = blockIdx.x, tid = threadIdx.x;
    const int lane = tid & 31, warp = tid >> 5;
    if (tid == 0) sh_cb = 0;
    __syncthreads();

    int rbase = tid * 4;
    int v[4];
#pragma unroll
    for (int j = 0; j < 4; j++) v[j] = g_hist[b * NB + (NB - 1 - (rbase + j))];
    v[1] += v[0]; v[2] += v[1]; v[3] += v[2];
    int tot = v[3];
#pragma unroll
    for (int o = 1; o < 32; o <<= 1) {
        int n = __shfl_up_sync(0xffffffffu, tot, o);
        if (lane >= o) tot += n;
    }
    if (lane == 31) wsum[warp] = tot;
    __syncthreads();
    if (warp == 0) {
        int w = wsum[lane];
#pragma unroll
        for (int o = 1; o < 32; o <<= 1) {
            int n = __shfl_up_sync(0xffffffffu, w, o);
            if (lane >= o) w += n;
        }
        wsum[lane] = w;
    }
    __syncthreads();
    int pre = (warp ? wsum[warp - 1] : 0) + (tot - v[3]);
#pragma unroll
    for (int j = 0; j < 4; j++) suf[NB - 1 - (rbase + j)] = pre + v[j];
    __syncthreads();
    if (tid == 0) suf[0] = NPRIOR;
    __syncthreads();
    int local = -1;
#pragma unroll
    for (int j = 0; j < 4; j++) {
        int bin = NB - 1 - (rbase + j);
        if (bin >= 1 && suf[bin] >= TOPK && bin > local) local = bin;
    }
    if (local >= 0) atomicMax(&sh_cb, local);
    __syncthreads();
    int cb = sh_cb; if (cb < 1) cb = 1;
    int ctot = suf[cb]; if (ctot > CANDS) ctot = CANDS;
    if (tid == 0) {
        g_cb[b] = cb;
        g_ctot[b] = ctot;
        g_suf[b * (NB + 2) + NB] = 0;
        g_suf[b * (NB + 2) + NB + 1] = 0;
    }
    for (int i = tid; i < NB; i += 1024) {
        g_suf[b * (NB + 2) + i] = suf[i];
        g_bincur[b * NB + i] = 0;
        g_hist[b * NB + i] = 0;          // restore zero-invariant
    }
    for (int r = ctot + tid; r < TOPK; r += 1024) {
        g_top[(size_t)b * TOPK + r] = 0ull;
        g_boxes[(size_t)b * TOPK + r] = make_float4(0.f, 0.f, 0.f, 0.f);
    }
}

// ---------------- K3: recompute keys from cls/obj, scatter to g_cand ----------------
__global__ void k3_compact(const float* __restrict__ cls, const float* __restrict__ obj) {
    int t4 = blockIdx.x * blockDim.x + threadIdx.x;
    if (t4 >= BATCH * NPRIOR / 4) return;
    int base = t4 * 4;
    int b = base / NPRIOR;
    int i0 = base - b * NPRIOR;
    int cb = g_cb[b];
    float4 c = *(const float4*)(cls + base);
    float4 o = *(const float4*)(obj + base);
    float sv[4] = {sqrtf(c.x * o.x), sqrtf(c.y * o.y), sqrtf(c.z * o.z), sqrtf(c.w * o.w)};
#pragma unroll
    for (int j = 0; j < 4; j++) {
        float m = sv[j];
        if (!(m > CONF_TH)) continue;
        int bin = bin_of(m);
        if (bin < cb) continue;
        int pos = g_suf[b * (NB + 2) + bin + 1] + atomicAdd(&g_bincur[b * NB + bin], 1);
        if (pos < CANDS) {
            ull key = ((ull)key_from_float(m) << 32) | (unsigned)(~(unsigned)(i0 + j));
            g_cand[(size_t)b * CANDS + pos] = key;
        }
    }
}

// ---------------- K4: exact in-bin rank + decode ----------------
__global__ void k4_rank(const float* __restrict__ bbox) {
    int t = blockIdx.x * blockDim.x + threadIdx.x;
    int b = t / CANDS;
    if (b >= BATCH) return;
    int s = t - b * CANDS;
    int ct = g_ctot[b];
    if (s >= ct) return;
    const ull* cand = g_cand + (size_t)b * CANDS;
    ull key = __ldg(cand + s);
    float m = float_from_key((unsigned)(key >> 32));
    int bin = bin_of(m);
    const int* suf = g_suf + b * (NB + 2);
    int st = suf[bin + 1];
    int en = suf[bin]; if (en > ct) en = ct;
    int r = st;
    for (int q = st; q < en; q++)
        if (__ldg(cand + q) > key) r++;
    if (r >= TOPK) return;
    g_top[(size_t)b * TOPK + r] = key;
    unsigned idx = ~(unsigned)key;
    float px, py, ps; prior_of(idx, px, py, ps);
    const float* bb = bbox + ((size_t)b * NPRIOR + idx) * 4;
    float cx = px + bb[0] * ps;
    float cy = py + bb[1] * ps;
    float w  = ps * expf(bb[2]);
    float h  = ps * expf(bb[3]);
    float x1 = cx - w * 0.5f, y1 = cy - h * 0.5f;
    g_boxes[(size_t)b * TOPK + r] = make_float4(x1, x1 + w, y1, y1 + h);
}

// ---------------- K5: NMS, block-parallel phase-1, smem-resident boxes ----------------
#define OFF_SBOX   0                      // float4[5120] = 81920
#define OFF_SVAL   81920                  // u8[5120]     = 5120
#define OFF_COLBOX 87040                  // float4[20*160] = 51200
#define OFF_LARGE  138240                 // float4[256]  = 4096
#define OFF_KPOS   142336                 // u16[896]     = 1792
#define OFF_KEEPF  144128                 // u8[5000]     = 5000
#define SMEM_K5    149128

extern __shared__ char smem[];

__global__ __launch_bounds__(1024, 1)
void k5_nms(const float* __restrict__ bbox, const float* __restrict__ kps,
            float* __restrict__ out, int write_valid) {
    float4* sbox  = (float4*)(smem + OFF_SBOX);
    unsigned char* svalid = (unsigned char*)(smem + OFF_SVAL);
    float4* colbox= (float4*)(smem + OFF_COLBOX);
    float4* large = (float4*)(smem + OFF_LARGE);
    unsigned short* kpos = (unsigned short*)(smem + OFF_KPOS);
    unsigned char*  keepf= (unsigned char*) (smem + OFF_KEEPF);

    __shared__ int wsum[32];
    __shared__ ull ovLoS[128];
    __shared__ ull ovHiS[128];
    __shared__ unsigned char statS[128];
    __shared__ int keptCount;
    __shared__ int colcnt[NCOL];
    __shared__ int lcnt;

    const int b = blockIdx.x, tid = threadIdx.x;
    const int lane = tid & 31, warp = tid >> 5;
    const size_t bT = (size_t)b * TOPK;
    const size_t boff = (size_t)b * NPRIOR;

    for (int i = tid; i < TOPK; i += 1024) {
        sbox[i] = g_boxes[bT + i];
        svalid[i] = ((unsigned)(g_top[bT + i] >> 32)) > KEYTH;
        keepf[i] = 0;
    }
    for (int i = TOPK + tid; i < SPAD; i += 1024) {
        sbox[i] = make_float4(0.f, 0.f, 0.f, 0.f);
        svalid[i] = 0;
    }
    if (tid == 0) { keptCount = 0; lcnt = 0; }
    if (tid < NCOL) colcnt[tid] = 0;
    __syncthreads();

    for (int base = 0; base < TOPK; base += 128) {
        // ---- init chunk state ----
        if (tid < 128) {
            ovLoS[tid] = 0ull;
            ovHiS[tid] = 0ull;
            statS[tid] = svalid[base + tid];
        }
        __syncthreads();

        // ---- phase 1a: in-chunk overlap matrix, flat over all 1024 threads ----
        // pair slot p = i*128 + j, test only j < i (earlier suppresses later)
        for (int pidx = tid; pidx < 128 * 128; pidx += 1024) {
            int i = pidx >> 7;
            int j = pidx & 127;
            if (j >= i) continue;
            float4 bi = sbox[base + i];
            float ai = (bi.y - bi.x) * (bi.w - bi.z);
            if (pair_sup(sbox[base + j], bi, ai)) {
                if (j < 64) atomicOr(&ovLoS[i], 1ull << j);
                else        atomicOr(&ovHiS[i], 1ull << (j - 64));
            }
        }

        // ---- phase 1b: kept-list scan, 8 threads per candidate ----
        {
            int ci = tid >> 3, sub = tid & 7;
            int p = base + ci;
            float4 bj = sbox[p];
            float aj = (bj.y - bj.x) * (bj.w - bj.z);
            bool sup = false;
            int c0 = colclamp(bj.x), c1 = colclamp(bj.y);
            for (int c = c0; c <= c1; c++) {
                int n = colcnt[c];
                const float4* cp = colbox + c * COLCAP;
                for (int m = sub; m < n; m += 8)
                    sup |= pair_sup(cp[m], bj, aj);
            }
            {
                int n = lcnt;
                for (int m = sub; m < n; m += 8)
                    sup |= pair_sup(large[m], bj, aj);
            }
            if (sup) statS[ci] = 0;    // all writers write 0: race-safe
        }
        __syncthreads();

        // ---- resolution: warp 0, 128-bit masks (unchanged) ----
        if (warp == 0) {
            unsigned s0 = __ballot_sync(0xffffffffu, statS[lane]);
            unsigned s1 = __ballot_sync(0xffffffffu, statS[32 + lane]);
            unsigned s2 = __ballot_sync(0xffffffffu, statS[64 + lane]);
            unsigned s3 = __ballot_sync(0xffffffffu, statS[96 + lane]);
            ull aliveLo = (ull)s0 | ((ull)s1 << 32);
            ull aliveHi = (ull)s2 | ((ull)s3 << 32);
            bool cf0, cf1, cf2, cf3;
            {
                int i0 = lane, i1 = 32 + lane, i2 = 64 + lane, i3 = 96 + lane;
                cf0 = ((aliveLo >> i0) & 1ull) && ((ovLoS[i0] & aliveLo) | (ovHiS[i0] & aliveHi));
                cf1 = ((aliveLo >> i1) & 1ull) && ((ovLoS[i1] & aliveLo) | (ovHiS[i1] & aliveHi));
                cf2 = ((aliveHi >> (i2 - 64)) & 1ull) && ((ovLoS[i2] & aliveLo) | (ovHiS[i2] & aliveHi));
                cf3 = ((aliveHi >> (i3 - 64)) & 1ull) && ((ovLoS[i3] & aliveLo) | (ovHiS[i3] & aliveHi));
            }
            unsigned c0b = __ballot_sync(0xffffffffu, cf0);
            unsigned c1b = __ballot_sync(0xffffffffu, cf1);
            unsigned c2b = __ballot_sync(0xffffffffu, cf2);
            unsigned c3b = __ballot_sync(0xffffffffu, cf3);
            ull confLo = (ull)c0b | ((ull)c1b << 32);
            ull confHi = (ull)c2b | ((ull)c3b << 32);
            ull keepLo = aliveLo & ~confLo;
            ull keepHi = aliveHi & ~confHi;
            ull pLo = confLo, pHi = confHi;
            while (pLo | pHi) {
                int i;
                if (pLo) { i = __ffsll((long long)pLo) - 1; pLo &= pLo - 1; }
                else     { i = 64 + __ffsll((long long)pHi) - 1; pHi &= pHi - 1; }
                if (((ovLoS[i] & keepLo) | (ovHiS[i] & keepHi)) == 0ull) {
                    if (i < 64) keepLo |= 1ull << i; else keepHi |= 1ull << (i - 64);
                }
            }
            int b0 = keptCount;
            int totalKeep = __popcll(keepLo) + __popcll(keepHi);
            int nLo = __popcll(keepLo);
#pragma unroll
            for (int k = 0; k < 4; k++) {
                int ci = k * 32 + lane;
                int p = base + ci;
                bool kk = (ci < 64) ? ((keepLo >> ci) & 1ull) : ((keepHi >> (ci - 64)) & 1ull);
                if (p < TOPK) keepf[p] = kk ? 1 : 0;
                if (kk) {
                    int off = (ci < 64) ? __popcll(keepLo & ((1ull << ci) - 1ull))
                                        : nLo + __popcll(keepHi & ((1ull << (ci - 64)) - 1ull));
                    kpos[b0 + off] = (unsigned short)p;
                    float4 bl = sbox[p];
                    int cc0 = colclamp(bl.x), cc1 = colclamp(bl.y);
                    if (cc1 - cc0 >= 3) {
                        int d = atomicAdd(&lcnt, 1);
                        if (d < LARGECAP) large[d] = bl;
                    } else {
                        for (int c = cc0; c <= cc1; c++) {
                            int d = atomicAdd(&colcnt[c], 1);
                            if (d < COLCAP) colbox[c * COLCAP + d] = bl;
                            else { int e = atomicAdd(&lcnt, 1); if (e < LARGECAP) large[e] = bl; }
                        }
                    }
                }
            }
            if (lane == 0) keptCount = b0 + totalKeep;
        }
        __syncthreads();
        if (keptCount >= KEEPK) break;
    }
    __syncthreads();

    int kc = keptCount;
    int kout = kc < KEEPK ? kc : KEEPK;

    // parallel filler: first (KEEPK-kc) non-kept positions, in order
    if (kc < KEEPK) {
        int need = KEEPK - kc;
        int j0 = tid * 5;
        int cnt = 0;
#pragma unroll
        for (int j = 0; j < 5; j++) {
            int p = j0 + j;
            if (p < TOPK && !keepf[p]) cnt++;
        }
        int x = cnt;
#pragma unroll
        for (int o = 1; o < 32; o <<= 1) {
            int n = __shfl_up_sync(0xffffffffu, x, o);
            if (lane >= o) x += n;
        }
        if (lane == 31) wsum[warp] = x;
        __syncthreads();
        if (warp == 0) {
            int w = wsum[lane];
#pragma unroll
            for (int o = 1; o < 32; o <<= 1) {
                int n = __shfl_up_sync(0xffffffffu, w, o);
                if (lane >= o) w += n;
            }
            wsum[lane] = w;
        }
        __syncthreads();
        int pre = (warp ? wsum[warp - 1] : 0) + (x - cnt);
#pragma unroll
        for (int j = 0; j < 5; j++) {
            int p = j0 + j;
            if (p < TOPK && !keepf[p]) {
                if (pre < need) kpos[kc + pre] = (unsigned short)p;
                pre++;
            }
        }
    }
    __syncthreads();

    // write final 750 rows
    for (int r = tid; r < KEEPK; r += 1024) {
        int pos = kpos[r];
        ull key = g_top[bT + pos];
        unsigned idx = ~(unsigned)key;
        unsigned hk = (unsigned)(key >> 32);
        float score = __uint_as_float((hk & 0x80000000u) ? (hk ^ 0x80000000u) : ~hk);
        float px, py, ps; prior_of(idx, px, py, ps);
        const float* bb = bbox + (boff + idx) * 4;
        float cx = px + bb[0] * ps, cy = py + bb[1] * ps;
        float w = ps * expf(bb[2]), h = ps * expf(bb[3]);
        float x1 = cx - w * 0.5f, y1 = cy - h * 0.5f;
        size_t t = (size_t)b * KEEPK + r;
        float* o = out + t * 15;
        o[0] = x1; o[1] = y1; o[2] = x1 + w; o[3] = y1 + h;
        const float* kp = kps + (boff + idx) * 10;
#pragma unroll
        for (int m = 0; m < 5; m++) {
            o[4 + 2 * m] = px + kp[2 * m] * ps;
            o[5 + 2 * m] = py + kp[2 * m + 1] * ps;
        }
        o[14] = score;
        if (write_valid)
            out[(size_t)BATCH * KEEPK * 15 + t] = (r < kout) ? 1.0f : 0.0f;
    }
}

// ---------------- launch ----------------
extern "C" void kernel_launch(void* const* d_in, const int* in_sizes, int n_in,
                              void* d_out, int out_size) {
    const float* cls  = (const float*)d_in[0];
    const float* obj  = (const float*)d_in[1];
    const float* bbox = (const float*)d_in[2];
    const float* kps  = (const float*)d_in[3];
    float* out = (float*)d_out;

    static int attr_set = 0;
    if (!attr_set) {
        cudaFuncSetAttribute(k5_nms, cudaFuncAttributeMaxDynamicSharedMemorySize, SMEM_K5);
        attr_set = 1;
    }

    k1_hist<<<(BATCH * NPRIOR / 4 + 255) / 256, 256>>>(cls, obj);
    k2_scan<<<BATCH, 1024>>>();
    k3_compact<<<(BATCH * NPRIOR / 4 + 255) / 256, 256>>>(cls, obj);
    k4_rank<<<(BATCH * CANDS + 511) / 512, 512>>>(bbox);

    int write_valid = (out_size >= BATCH * KEEPK * 16) ? 1 : 0;
    k5_nms<<<BATCH, 1024, SMEM_K5>>>(bbox, kps, out, write_valid);
}

// round 16
// speedup vs baseline: 1.0661x; 1.0336x over previous
#include <cuda_runtime.h>
#include <stdint.h>

#define BATCH   8
#define NPRIOR  33600
#define TOPK    5000
#define KEEPK   750
#define CONF_TH 0.3f
#define NMS_TH  0.3f
#define NB      4096
#define CANDS   6144
#define BINSCALE (4094.0f / 0.7f)
#define KEYTH   0xBE99999Au     // key_from_float(0.3f)

#define NCOL    20
#define COLCAP  160
#define LARGECAP 256
#define INVCOLW (1.0f / 64.0f)
#define SPAD    5120            // TOPK padded to chunk multiple (128)
#define K4THR   512
#define WINCAP  2048            // shared comparison-window capacity (keys)

typedef unsigned long long ull;

// ---------------- device scratch ----------------
__device__ int    g_hist[BATCH * NB];        // zero at load; every pass restores zero
__device__ int    g_bincur[BATCH * NB];
__device__ int    g_suf[BATCH * (NB + 2)];
__device__ int    g_cb[BATCH];
__device__ int    g_ctot[BATCH];
__device__ ull    g_cand[(size_t)BATCH * CANDS];
__device__ ull    g_top [(size_t)BATCH * TOPK];
__device__ float4 g_boxes[(size_t)BATCH * TOPK];

// ---------------- helpers ----------------
__device__ __forceinline__ unsigned key_from_float(float f) {
    unsigned u = __float_as_uint(f);
    return (u & 0x80000000u) ? ~u : (u | 0x80000000u);
}
__device__ __forceinline__ float float_from_key(unsigned u) {
    return __uint_as_float((u & 0x80000000u) ? (u ^ 0x80000000u) : ~u);
}
__device__ __forceinline__ int bin_of(float m) {
    if (!(m > CONF_TH)) return 0;
    int b = (int)((m - CONF_TH) * BINSCALE);
    if (b > 4094) b = 4094;
    return 1 + b;
}
__device__ __forceinline__ int colclamp(float x) {
    int c = (int)floorf(x * INVCOLW);
    return c < 0 ? 0 : (c > NCOL - 1 ? NCOL - 1 : c);
}
// box = (x1,x2,y1,y2); w,h>0 so reference clamps are identity; division exact
__device__ __forceinline__ bool pair_sup(float4 a, float4 b, float ab) {
    float xo = fminf(a.y, b.y) - fmaxf(a.x, b.x);
    float yo = fminf(a.w, b.w) - fmaxf(a.z, b.z);
    if (xo > 0.0f && yo > 0.0f) {
        float inter = xo * yo;
        float aa = (a.y - a.x) * (a.w - a.z);
        return inter / (aa + ab - inter + 1e-12f) > NMS_TH;
    }
    return false;
}
__device__ __forceinline__ void prior_of(unsigned idx, float& px, float& py, float& ps) {
    if (idx < 25600u)      { ps = 8.0f;  px = (float)((idx % 160u) * 8u); py = (float)((idx / 160u) * 8u); }
    else if (idx < 32000u) { unsigned j = idx - 25600u; ps = 16.0f; px = (float)((j % 80u) * 16u); py = (float)((j / 80u) * 16u); }
    else                   { unsigned j = idx - 32000u; ps = 32.0f; px = (float)((j % 40u) * 32u); py = (float)((j / 40u) * 32u); }
}

// ---------------- K1: histogram only (no key store) ----------------
__global__ void k1_hist(const float* __restrict__ cls, const float* __restrict__ obj) {
    int t4 = blockIdx.x * blockDim.x + threadIdx.x;
    if (t4 >= BATCH * NPRIOR / 4) return;
    int base = t4 * 4;
    int b = base / NPRIOR;           // NPRIOR % 4 == 0 -> all 4 in same batch
    float4 c = *(const float4*)(cls + base);
    float4 o = *(const float4*)(obj + base);
    float sv[4] = {sqrtf(c.x * o.x), sqrtf(c.y * o.y), sqrtf(c.z * o.z), sqrtf(c.w * o.w)};
#pragma unroll
    for (int j = 0; j < 4; j++)
        if (sv[j] > CONF_TH) atomicAdd(&g_hist[b * NB + bin_of(sv[j])], 1);
}

// ---------------- K2: suffix scan + cutoff; re-zeros g_hist ----------------
__global__ __launch_bounds__(1024, 1) void k2_scan() {
    __shared__ int suf[NB];
    __shared__ int wsum[32];
    __shared__ int sh_cb;
    const int b = blockIdx.x, tid = threadIdx.x;
    const int lane = tid & 31, warp = tid >> 5;
    if (tid == 0) sh_cb = 0;
    __syncthreads();

    int rbase = tid * 4;
    int v[4];
#pragma unroll
    for (int j = 0; j < 4; j++) v[j] = g_hist[b * NB + (NB - 1 - (rbase + j))];
    v[1] += v[0]; v[2] += v[1]; v[3] += v[2];
    int tot = v[3];
#pragma unroll
    for (int o = 1; o < 32; o <<= 1) {
        int n = __shfl_up_sync(0xffffffffu, tot, o);
        if (lane >= o) tot += n;
    }
    if (lane == 31) wsum[warp] = tot;
    __syncthreads();
    if (warp == 0) {
        int w = wsum[lane];
#pragma unroll
        for (int o = 1; o < 32; o <<= 1) {
            int n = __shfl_up_sync(0xffffffffu, w, o);
            if (lane >= o) w += n;
        }
        wsum[lane] = w;
    }
    __syncthreads();
    int pre = (warp ? wsum[warp - 1] : 0) + (tot - v[3]);
#pragma unroll
    for (int j = 0; j < 4; j++) suf[NB - 1 - (rbase + j)] = pre + v[j];
    __syncthreads();
    if (tid == 0) suf[0] = NPRIOR;
    __syncthreads();
    int local = -1;
#pragma unroll
    for (int j = 0; j < 4; j++) {
        int bin = NB - 1 - (rbase + j);
        if (bin >= 1 && suf[bin] >= TOPK && bin > local) local = bin;
    }
    if (local >= 0) atomicMax(&sh_cb, local);
    __syncthreads();
    int cb = sh_cb; if (cb < 1) cb = 1;
    int ctot = suf[cb]; if (ctot > CANDS) ctot = CANDS;
    if (tid == 0) {
        g_cb[b] = cb;
        g_ctot[b] = ctot;
        g_suf[b * (NB + 2) + NB] = 0;
        g_suf[b * (NB + 2) + NB + 1] = 0;
    }
    for (int i = tid; i < NB; i += 1024) {
        g_suf[b * (NB + 2) + i] = suf[i];
        g_bincur[b * NB + i] = 0;
        g_hist[b * NB + i] = 0;          // restore zero-invariant
    }
    for (int r = ctot + tid; r < TOPK; r += 1024) {
        g_top[(size_t)b * TOPK + r] = 0ull;
        g_boxes[(size_t)b * TOPK + r] = make_float4(0.f, 0.f, 0.f, 0.f);
    }
}

// ---------------- K3: recompute keys from cls/obj, scatter to g_cand ----------------
__global__ void k3_compact(const float* __restrict__ cls, const float* __restrict__ obj) {
    int t4 = blockIdx.x * blockDim.x + threadIdx.x;
    if (t4 >= BATCH * NPRIOR / 4) return;
    int base = t4 * 4;
    int b = base / NPRIOR;
    int i0 = base - b * NPRIOR;
    int cb = g_cb[b];
    float4 c = *(const float4*)(cls + base);
    float4 o = *(const float4*)(obj + base);
    float sv[4] = {sqrtf(c.x * o.x), sqrtf(c.y * o.y), sqrtf(c.z * o.z), sqrtf(c.w * o.w)};
#pragma unroll
    for (int j = 0; j < 4; j++) {
        float m = sv[j];
        if (!(m > CONF_TH)) continue;
        int bin = bin_of(m);
        if (bin < cb) continue;
        int pos = g_suf[b * (NB + 2) + bin + 1] + atomicAdd(&g_bincur[b * NB + bin], 1);
        if (pos < CANDS) {
            ull key = ((ull)key_from_float(m) << 32) | (unsigned)(~(unsigned)(i0 + j));
            g_cand[(size_t)b * CANDS + pos] = key;
        }
    }
}

// ---------------- K4: exact in-bin rank + decode (shared comparison window) ----------------
__global__ __launch_bounds__(K4THR) void k4_rank(const float* __restrict__ bbox) {
    __shared__ ull win[WINCAP];
    __shared__ int s_lo, s_hi;
    const int tid = threadIdx.x;
    const int blk = blockIdx.x;
    const int b = blk / (CANDS / K4THR);           // CANDS % K4THR == 0
    const int s0 = (blk % (CANDS / K4THR)) * K4THR;
    const int ct = g_ctot[b];
    if (s0 >= ct) return;                          // whole block inactive (uniform)
    const ull* cand = g_cand + (size_t)b * CANDS;
    const int* suf = g_suf + b * (NB + 2);

    if (tid == 0) { s_lo = 0x7FFFFFFF; s_hi = 0; }
    __syncthreads();

    int s = s0 + tid;
    bool active = s < ct;
    ull key = 0; int st = 0, en = 0;
    if (active) {
        key = cand[s];                              // coalesced
        float m = float_from_key((unsigned)(key >> 32));
        int bin = bin_of(m);
        st = suf[bin + 1];
        en = suf[bin]; if (en > ct) en = ct;
        atomicMin(&s_lo, st);
        atomicMax(&s_hi, en);
    }
    __syncthreads();
    int wlo = s_lo, whi = s_hi;
    int wcnt = whi - wlo;
    bool sh_ok = (wcnt > 0 && wcnt <= WINCAP);
    if (sh_ok)
        for (int i = tid; i < wcnt; i += K4THR) win[i] = cand[wlo + i];   // coalesced
    __syncthreads();
    if (!active) return;

    int r = st;
    if (sh_ok) {
        for (int q = st; q < en; q++)
            if (win[q - wlo] > key) r++;
    } else {
        for (int q = st; q < en; q++)
            if (__ldg(cand + q) > key) r++;
    }
    if (r >= TOPK) return;
    g_top[(size_t)b * TOPK + r] = key;
    unsigned idx = ~(unsigned)key;
    float px, py, ps; prior_of(idx, px, py, ps);
    const float* bb = bbox + ((size_t)b * NPRIOR + idx) * 4;
    float cx = px + bb[0] * ps;
    float cy = py + bb[1] * ps;
    float w  = ps * expf(bb[2]);
    float h  = ps * expf(bb[3]);
    float x1 = cx - w * 0.5f, y1 = cy - h * 0.5f;
    g_boxes[(size_t)b * TOPK + r] = make_float4(x1, x1 + w, y1, y1 + h);
}

// ---------------- K5: NMS, 128-wide chunks, smem-resident boxes (R13 verbatim) ----------------
#define OFF_SBOX   0                      // float4[5120] = 81920
#define OFF_SVAL   81920                  // u8[5120]     = 5120
#define OFF_COLBOX 87040                  // float4[20*160] = 51200
#define OFF_LARGE  138240                 // float4[256]  = 4096
#define OFF_KPOS   142336                 // u16[896]     = 1792
#define OFF_KEEPF  144128                 // u8[5000]     = 5000
#define SMEM_K5    149128

extern __shared__ char smem[];

__global__ __launch_bounds__(1024, 1)
void k5_nms(const float* __restrict__ bbox, const float* __restrict__ kps,
            float* __restrict__ out, int write_valid) {
    float4* sbox  = (float4*)(smem + OFF_SBOX);
    unsigned char* svalid = (unsigned char*)(smem + OFF_SVAL);
    float4* colbox= (float4*)(smem + OFF_COLBOX);
    float4* large = (float4*)(smem + OFF_LARGE);
    unsigned short* kpos = (unsigned short*)(smem + OFF_KPOS);
    unsigned char*  keepf= (unsigned char*) (smem + OFF_KEEPF);

    __shared__ int wsum[32];
    __shared__ ull ovLoS[128];
    __shared__ ull ovHiS[128];
    __shared__ unsigned char statS[128];
    __shared__ int keptCount;
    __shared__ int colcnt[NCOL];
    __shared__ int lcnt;

    const int b = blockIdx.x, tid = threadIdx.x;
    const int lane = tid & 31, warp = tid >> 5;
    const size_t bT = (size_t)b * TOPK;
    const size_t boff = (size_t)b * NPRIOR;

    for (int i = tid; i < TOPK; i += 1024) {
        sbox[i] = g_boxes[bT + i];
        svalid[i] = ((unsigned)(g_top[bT + i] >> 32)) > KEYTH;
        keepf[i] = 0;
    }
    for (int i = TOPK + tid; i < SPAD; i += 1024) {
        sbox[i] = make_float4(0.f, 0.f, 0.f, 0.f);
        svalid[i] = 0;
    }
    if (tid == 0) { keptCount = 0; lcnt = 0; }
    if (tid < NCOL) colcnt[tid] = 0;
    __syncthreads();

    for (int base = 0; base < TOPK; base += 128) {
#pragma unroll
        for (int q = 0; q < 4; q++) {
            const int ci = q * 32 + warp;
            const int p = base + ci;
            float4 bj = sbox[p];
            float aj = (bj.y - bj.x) * (bj.w - bj.z);
            unsigned m0 = 0, m1 = 0, m2 = 0, m3 = 0;
            for (int q2 = 0; q2 <= q; q2++) {
                bool ob;
                if (q2 < q) ob = pair_sup(sbox[base + q2 * 32 + lane], bj, aj);
                else        ob = (lane < warp) ? pair_sup(sbox[base + q * 32 + lane], bj, aj) : false;
                unsigned bal = __ballot_sync(0xffffffffu, ob);
                if (q2 == 0) m0 = bal; else if (q2 == 1) m1 = bal;
                else if (q2 == 2) m2 = bal; else m3 = bal;
            }
            bool sup = false;
            int c0 = colclamp(bj.x), c1 = colclamp(bj.y);
            for (int c = c0; c <= c1; c++) {
                int n = colcnt[c];
                const float4* cp = colbox + c * COLCAP;
                for (int m = lane; m < n; m += 32)
                    sup |= pair_sup(cp[m], bj, aj);
            }
            {
                int n = lcnt;
                for (int m = lane; m < n; m += 32)
                    sup |= pair_sup(large[m], bj, aj);
            }
            sup = __any_sync(0xffffffffu, sup);
            if (lane == 0) {
                ovLoS[ci] = (ull)m0 | ((ull)m1 << 32);
                ovHiS[ci] = (ull)m2 | ((ull)m3 << 32);
                statS[ci] = (svalid[p] && !sup) ? 1 : 0;
            }
        }
        __syncthreads();

        if (warp == 0) {
            unsigned s0 = __ballot_sync(0xffffffffu, statS[lane]);
            unsigned s1 = __ballot_sync(0xffffffffu, statS[32 + lane]);
            unsigned s2 = __ballot_sync(0xffffffffu, statS[64 + lane]);
            unsigned s3 = __ballot_sync(0xffffffffu, statS[96 + lane]);
            ull aliveLo = (ull)s0 | ((ull)s1 << 32);
            ull aliveHi = (ull)s2 | ((ull)s3 << 32);
            bool cf0, cf1, cf2, cf3;
            {
                int i0 = lane, i1 = 32 + lane, i2 = 64 + lane, i3 = 96 + lane;
                cf0 = ((aliveLo >> i0) & 1ull) && ((ovLoS[i0] & aliveLo) | (ovHiS[i0] & aliveHi));
                cf1 = ((aliveLo >> i1) & 1ull) && ((ovLoS[i1] & aliveLo) | (ovHiS[i1] & aliveHi));
                cf2 = ((aliveHi >> (i2 - 64)) & 1ull) && ((ovLoS[i2] & aliveLo) | (ovHiS[i2] & aliveHi));
                cf3 = ((aliveHi >> (i3 - 64)) & 1ull) && ((ovLoS[i3] & aliveLo) | (ovHiS[i3] & aliveHi));
            }
            unsigned c0b = __ballot_sync(0xffffffffu, cf0);
            unsigned c1b = __ballot_sync(0xffffffffu, cf1);
            unsigned c2b = __ballot_sync(0xffffffffu, cf2);
            unsigned c3b = __ballot_sync(0xffffffffu, cf3);
            ull confLo = (ull)c0b | ((ull)c1b << 32);
            ull confHi = (ull)c2b | ((ull)c3b << 32);
            ull keepLo = aliveLo & ~confLo;
            ull keepHi = aliveHi & ~confHi;
            ull pLo = confLo, pHi = confHi;
            while (pLo | pHi) {
                int i;
                if (pLo) { i = __ffsll((long long)pLo) - 1; pLo &= pLo - 1; }
                else     { i = 64 + __ffsll((long long)pHi) - 1; pHi &= pHi - 1; }
                if (((ovLoS[i] & keepLo) | (ovHiS[i] & keepHi)) == 0ull) {
                    if (i < 64) keepLo |= 1ull << i; else keepHi |= 1ull << (i - 64);
                }
            }
            int b0 = keptCount;
            int totalKeep = __popcll(keepLo) + __popcll(keepHi);
            int nLo = __popcll(keepLo);
#pragma unroll
            for (int k = 0; k < 4; k++) {
                int ci = k * 32 + lane;
                int p = base + ci;
                bool kk = (ci < 64) ? ((keepLo >> ci) & 1ull) : ((keepHi >> (ci - 64)) & 1ull);
                if (p < TOPK) keepf[p] = kk ? 1 : 0;
                if (kk) {
                    int off = (ci < 64) ? __popcll(keepLo & ((1ull << ci) - 1ull))
                                        : nLo + __popcll(keepHi & ((1ull << (ci - 64)) - 1ull));
                    kpos[b0 + off] = (unsigned short)p;
                    float4 bl = sbox[p];
                    int cc0 = colclamp(bl.x), cc1 = colclamp(bl.y);
                    if (cc1 - cc0 >= 3) {
                        int d = atomicAdd(&lcnt, 1);
                        if (d < LARGECAP) large[d] = bl;
                    } else {
                        for (int c = cc0; c <= cc1; c++) {
                            int d = atomicAdd(&colcnt[c], 1);
                            if (d < COLCAP) colbox[c * COLCAP + d] = bl;
                            else { int e = atomicAdd(&lcnt, 1); if (e < LARGECAP) large[e] = bl; }
                        }
                    }
                }
            }
            if (lane == 0) keptCount = b0 + totalKeep;
        }
        __syncthreads();
        if (keptCount >= KEEPK) break;
    }
    __syncthreads();

    int kc = keptCount;
    int kout = kc < KEEPK ? kc : KEEPK;

    // parallel filler: first (KEEPK-kc) non-kept positions, in order
    if (kc < KEEPK) {
        int need = KEEPK - kc;
        int j0 = tid * 5;
        int cnt = 0;
#pragma unroll
        for (int j = 0; j < 5; j++) {
            int p = j0 + j;
            if (p < TOPK && !keepf[p]) cnt++;
        }
        int x = cnt;
#pragma unroll
        for (int o = 1; o < 32; o <<= 1) {
            int n = __shfl_up_sync(0xffffffffu, x, o);
            if (lane >= o) x += n;
        }
        if (lane == 31) wsum[warp] = x;
        __syncthreads();
        if (warp == 0) {
            int w = wsum[lane];
#pragma unroll
            for (int o = 1; o < 32; o <<= 1) {
                int n = __shfl_up_sync(0xffffffffu, w, o);
                if (lane >= o) w += n;
            }
            wsum[lane] = w;
        }
        __syncthreads();
        int pre = (warp ? wsum[warp - 1] : 0) + (x - cnt);
#pragma unroll
        for (int j = 0; j < 5; j++) {
            int p = j0 + j;
            if (p < TOPK && !keepf[p]) {
                if (pre < need) kpos[kc + pre] = (unsigned short)p;
                pre++;
            }
        }
    }
    __syncthreads();

    // write final 750 rows
    for (int r = tid; r < KEEPK; r += 1024) {
        int pos = kpos[r];
        ull key = g_top[bT + pos];
        unsigned idx = ~(unsigned)key;
        unsigned hk = (unsigned)(key >> 32);
        float score = __uint_as_float((hk & 0x80000000u) ? (hk ^ 0x80000000u) : ~hk);
        float px, py, ps; prior_of(idx, px, py, ps);
        const float* bb = bbox + (boff + idx) * 4;
        float cx = px + bb[0] * ps, cy = py + bb[1] * ps;
        float w = ps * expf(bb[2]), h = ps * expf(bb[3]);
        float x1 = cx - w * 0.5f, y1 = cy - h * 0.5f;
        size_t t = (size_t)b * KEEPK + r;
        float* o = out + t * 15;
        o[0] = x1; o[1] = y1; o[2] = x1 + w; o[3] = y1 + h;
        const float* kp = kps + (boff + idx) * 10;
#pragma unroll
        for (int m = 0; m < 5; m++) {
            o[4 + 2 * m] = px + kp[2 * m] * ps;
            o[5 + 2 * m] = py + kp[2 * m + 1] * ps;
        }
        o[14] = score;
        if (write_valid)
            out[(size_t)BATCH * KEEPK * 15 + t] = (r < kout) ? 1.0f : 0.0f;
    }
}

// ---------------- launch ----------------
extern "C" void kernel_launch(void* const* d_in, const int* in_sizes, int n_in,
                              void* d_out, int out_size) {
    const float* cls  = (const float*)d_in[0];
    const float* obj  = (const float*)d_in[1];
    const float* bbox = (const float*)d_in[2];
    const float* kps  = (const float*)d_in[3];
    float* out = (float*)d_out;

    static int attr_set = 0;
    if (!attr_set) {
        cudaFuncSetAttribute(k5_nms, cudaFuncAttributeMaxDynamicSharedMemorySize, SMEM_K5);
        attr_set = 1;
    }

    k1_hist<<<(BATCH * NPRIOR / 4 + 255) / 256, 256>>>(cls, obj);
    k2_scan<<<BATCH, 1024>>>();
    k3_compact<<<(BATCH * NPRIOR / 4 + 255) / 256, 256>>>(cls, obj);
    k4_rank<<<BATCH * (CANDS / K4THR), K4THR>>>(bbox);

    int write_valid = (out_size >= BATCH * KEEPK * 16) ? 1 : 0;
    k5_nms<<<BATCH, 1024, SMEM_K5>>>(bbox, kps, out, write_valid);
}